// round 2
// baseline (speedup 1.0000x reference)
#include <cuda_runtime.h>
#include <cstdint>

#define KP 6
#define BB 256
#define DD 256
#define NN 50000
#define TOPK 5

#define BM 128
#define BN 128
#define BK 8
#define TM 8
#define TN 8

// inverse L2 norms
__device__ float g_invF[KP * BB];
__device__ float g_invM[KP * NN];
// fallback sim scratch in case d_out only holds soft_labels
__device__ float g_simScratch[(size_t)KP * BB * NN];

// ---------------------------------------------------------------------------
// 1/max(||row||, eps), one warp per row of 256 floats
// ---------------------------------------------------------------------------
__global__ void rownorm_kernel(const float* __restrict__ x,
                               float* __restrict__ inv, int rows) {
    int warp = (blockIdx.x * blockDim.x + threadIdx.x) >> 5;
    int lane = threadIdx.x & 31;
    if (warp >= rows) return;
    const float4* p = (const float4*)(x + (size_t)warp * DD);
    float4 v0 = p[lane];
    float4 v1 = p[lane + 32];
    float s = v0.x * v0.x + v0.y * v0.y + v0.z * v0.z + v0.w * v0.w
            + v1.x * v1.x + v1.y * v1.y + v1.z * v1.z + v1.w * v1.w;
#pragma unroll
    for (int o = 16; o; o >>= 1) s += __shfl_xor_sync(0xFFFFFFFFu, s, o);
    if (lane == 0) inv[warp] = 1.0f / fmaxf(sqrtf(s), 1e-12f);
}

// ---------------------------------------------------------------------------
// Batched SGEMM: C[k,b,n] = dot(feat[k,b,:], mem[k,n,:]) * invF[k,b]*invM[k,n]
// 128x128 tile, BK=8, double-buffered smem, 8x8 microtile, 256 threads
// ---------------------------------------------------------------------------
__global__ void __launch_bounds__(256)
gemm_kernel(const float* __restrict__ A,   // [KP][BB][DD]
            const float* __restrict__ B,   // [KP][NN][DD]
            float* __restrict__ C,         // [KP][BB][NN]
            const float* __restrict__ invF,
            const float* __restrict__ invM) {
    const int k  = blockIdx.z;
    const int m0 = blockIdx.y * BM;
    const int n0 = blockIdx.x * BN;

    const float* Ak = A + (size_t)k * BB * DD;
    const float* Bk = B + (size_t)k * NN * DD;

    __shared__ float As[2][BK][BM];
    __shared__ float Bs[2][BK][BN];

    const int tid   = threadIdx.x;
    const int ldRow = tid >> 1;          // 0..127
    const int ldCol = (tid & 1) << 2;    // 0 or 4

    const int aRow = m0 + ldRow;                         // always < 256
    const int bRow = min(n0 + ldRow, NN - 1);            // clamp edge loads

    const float* aPtr = Ak + (size_t)aRow * DD + ldCol;
    const float* bPtr = Bk + (size_t)bRow * DD + ldCol;

    const int tx = tid & 15;   // n direction
    const int ty = tid >> 4;   // m direction

    float acc[TM][TN];
#pragma unroll
    for (int i = 0; i < TM; ++i)
#pragma unroll
        for (int j = 0; j < TN; ++j) acc[i][j] = 0.0f;

    // prologue: k-tile 0
    {
        float4 a4 = *(const float4*)aPtr;
        float4 b4 = *(const float4*)bPtr;
        As[0][ldCol + 0][ldRow] = a4.x;
        As[0][ldCol + 1][ldRow] = a4.y;
        As[0][ldCol + 2][ldRow] = a4.z;
        As[0][ldCol + 3][ldRow] = a4.w;
        Bs[0][ldCol + 0][ldRow] = b4.x;
        Bs[0][ldCol + 1][ldRow] = b4.y;
        Bs[0][ldCol + 2][ldRow] = b4.z;
        Bs[0][ldCol + 3][ldRow] = b4.w;
    }
    __syncthreads();

    int buf = 0;
    const int KT = DD / BK;  // 32
    for (int kt = 0; kt < KT; ++kt) {
        float4 na, nb;
        if (kt + 1 < KT) {
            na = *(const float4*)(aPtr + (kt + 1) * BK);
            nb = *(const float4*)(bPtr + (kt + 1) * BK);
        }
#pragma unroll
        for (int kk = 0; kk < BK; ++kk) {
            float ar[TM], br[TN];
            *(float4*)&ar[0] = *(const float4*)&As[buf][kk][ty * TM];
            *(float4*)&ar[4] = *(const float4*)&As[buf][kk][ty * TM + 4];
            *(float4*)&br[0] = *(const float4*)&Bs[buf][kk][tx * TN];
            *(float4*)&br[4] = *(const float4*)&Bs[buf][kk][tx * TN + 4];
#pragma unroll
            for (int i = 0; i < TM; ++i)
#pragma unroll
                for (int j = 0; j < TN; ++j)
                    acc[i][j] += ar[i] * br[j];
        }
        if (kt + 1 < KT) {
            int nbuf = buf ^ 1;
            As[nbuf][ldCol + 0][ldRow] = na.x;
            As[nbuf][ldCol + 1][ldRow] = na.y;
            As[nbuf][ldCol + 2][ldRow] = na.z;
            As[nbuf][ldCol + 3][ldRow] = na.w;
            Bs[nbuf][ldCol + 0][ldRow] = nb.x;
            Bs[nbuf][ldCol + 1][ldRow] = nb.y;
            Bs[nbuf][ldCol + 2][ldRow] = nb.z;
            Bs[nbuf][ldCol + 3][ldRow] = nb.w;
        }
        __syncthreads();
        buf ^= 1;
    }

    // epilogue: scale by inverse norms, write sim
    float im[TN];
#pragma unroll
    for (int j = 0; j < TN; ++j) {
        int n = n0 + tx * TN + j;
        im[j] = (n < NN) ? invM[k * NN + n] : 0.0f;
    }
#pragma unroll
    for (int i = 0; i < TM; ++i) {
        int m = m0 + ty * TM + i;
        float fi = invF[k * BB + m];
        float* Crow = C + (size_t)k * BB * NN + (size_t)m * NN;
#pragma unroll
        for (int j = 0; j < TN; j += 4) {
            int n = n0 + tx * TN + j;
            if (n + 3 < NN) {
                float4 o;
                o.x = acc[i][j + 0] * fi * im[j + 0];
                o.y = acc[i][j + 1] * fi * im[j + 1];
                o.z = acc[i][j + 2] * fi * im[j + 2];
                o.w = acc[i][j + 3] * fi * im[j + 3];
                *(float4*)(Crow + n) = o;
            } else {
#pragma unroll
                for (int jj = 0; jj < 4; ++jj)
                    if (n + jj < NN)
                        Crow[n + jj] = acc[i][j + jj] * fi * im[j + jj];
            }
        }
    }
}

// ---------------------------------------------------------------------------
// Per (k,b) row: top-5 of 50000, softmax over the 5, scatter into soft_labels
// (all other entries are exactly 0 in fp32, handled by memset)
// ---------------------------------------------------------------------------
__global__ void __launch_bounds__(256)
topk_kernel(const float* __restrict__ sim, float* __restrict__ soft) {
    const int row = blockIdx.x;  // 0 .. KP*BB-1
    const float* s = sim + (size_t)row * NN;
    const int tid = threadIdx.x;

    float tv[TOPK];
    int   ti[TOPK];
#pragma unroll
    for (int i = 0; i < TOPK; ++i) { tv[i] = -3.0e38f; ti[i] = -1; }

    auto insert = [&](float v, int idx) {
        if (v > tv[TOPK - 1]) {
            tv[TOPK - 1] = v; ti[TOPK - 1] = idx;
#pragma unroll
            for (int p = TOPK - 1; p > 0; --p) {
                if (tv[p] > tv[p - 1]) {
                    float t = tv[p]; tv[p] = tv[p - 1]; tv[p - 1] = t;
                    int   q = ti[p]; ti[p] = ti[p - 1]; ti[p - 1] = q;
                }
            }
        }
    };

    const float4* s4 = (const float4*)s;
    for (int i = tid; i < NN / 4; i += 256) {  // NN % 4 == 0
        float4 v = s4[i];
        int b = 4 * i;
        insert(v.x, b + 0);
        insert(v.y, b + 1);
        insert(v.z, b + 2);
        insert(v.w, b + 3);
    }

    __shared__ float sv[256 * TOPK];
    __shared__ int   si[256 * TOPK];
    __shared__ float rv[256];
    __shared__ int   ri[256];
    __shared__ float winV[TOPK];
    __shared__ int   winI[TOPK];

#pragma unroll
    for (int i = 0; i < TOPK; ++i) {
        sv[tid * TOPK + i] = tv[i];
        si[tid * TOPK + i] = ti[i];
    }
    __syncthreads();

    for (int r = 0; r < TOPK; ++r) {
        float m = -3.0e38f; int ms = -1;
#pragma unroll
        for (int j = 0; j < TOPK; ++j) {
            int slot = tid * TOPK + j;
            if (sv[slot] > m) { m = sv[slot]; ms = slot; }
        }
        rv[tid] = m; ri[tid] = ms;
        __syncthreads();
        for (int off = 128; off; off >>= 1) {
            if (tid < off && rv[tid + off] > rv[tid]) {
                rv[tid] = rv[tid + off]; ri[tid] = ri[tid + off];
            }
            __syncthreads();
        }
        if (tid == 0) {
            int slot = ri[0];
            winV[r] = rv[0];
            winI[r] = si[slot];
            sv[slot] = -3.0e38f;  // remove winner
        }
        __syncthreads();
    }

    if (tid == 0) {
        float mx = winV[0];
        float w[TOPK], sum = 0.0f;
#pragma unroll
        for (int i = 0; i < TOPK; ++i) {
            w[i] = __expf((winV[i] - mx) * (1.0f / 3.0f));
            sum += w[i];
        }
        float invSum = 1.0f / sum;
        float* srow = soft + (size_t)row * NN;
#pragma unroll
        for (int i = 0; i < TOPK; ++i)
            srow[winI[i]] = w[i] * invSum;
    }
}

// ---------------------------------------------------------------------------
extern "C" void kernel_launch(void* const* d_in, const int* in_sizes, int n_in,
                              void* d_out, int out_size) {
    const float* feat = (const float*)d_in[0];  // [KP,BB,DD]
    const float* mem  = (const float*)d_in[1];  // [KP,NN,DD]
    float* out = (float*)d_out;

    const size_t total = (size_t)KP * BB * NN;

    float *invF, *invM;
    cudaGetSymbolAddress((void**)&invF, g_invF);
    cudaGetSymbolAddress((void**)&invM, g_invM);

    float* soft = out;
    float* sim;
    if ((size_t)out_size >= 2 * total) {
        sim = out + total;  // outputs concatenated: (soft_labels, sim)
    } else {
        cudaGetSymbolAddress((void**)&sim, g_simScratch);
    }

    // zero soft_labels (non-top-5 softmax terms are exactly 0 in fp32)
    cudaMemsetAsync(soft, 0, total * sizeof(float), 0);

    // inverse norms
    {
        int rowsF = KP * BB;            // 1536 rows, 8 warps/block
        rownorm_kernel<<<(rowsF + 7) / 8, 256>>>(feat, invF, rowsF);
        int rowsM = KP * NN;            // 300000 rows
        rownorm_kernel<<<(rowsM + 7) / 8, 256>>>(mem, invM, rowsM);
    }

    // batched SGEMM with normalization epilogue
    {
        dim3 grid((NN + BN - 1) / BN, BB / BM, KP);  // (391, 2, 6)
        gemm_kernel<<<grid, 256>>>(feat, mem, sim, invF, invM);
    }

    // top-5 + softmax scatter
    topk_kernel<<<KP * BB, 256>>>(sim, soft);
}

// round 4
// speedup vs baseline: 2.6924x; 2.6924x over previous
#include <cuda_runtime.h>
#include <cuda_bf16.h>
#include <cstdint>

#define KP 6
#define BB 256
#define DD 256
#define NN 50000
#define TOPK 5

// ---------------------------------------------------------------------------
// static device scratch
// ---------------------------------------------------------------------------
__device__ float g_invF[KP * BB];
__device__ float g_invM[KP * NN];
__device__ __nv_bfloat16 g_Asplit[(size_t)KP * BB * 512];   // [k][m][hi(256)|lo(256)]
__device__ __nv_bfloat16 g_Bsplit[(size_t)KP * NN * 512];   // [k][n][hi(256)|lo(256)]
__device__ float g_simScratch[(size_t)KP * BB * NN];        // fallback only

// ---------------------------------------------------------------------------
// helpers
// ---------------------------------------------------------------------------
__device__ __forceinline__ uint32_t smem_u32(const void* p) {
    uint32_t a;
    asm("{ .reg .u64 t; cvta.to.shared.u64 t, %1; cvt.u32.u64 %0, t; }"
        : "=r"(a) : "l"(p));
    return a;
}

#define CP16(dst, src) \
    asm volatile("cp.async.cg.shared.global [%0], [%1], 16;" \
                 :: "r"(dst), "l"(src) : "memory")
#define CP_COMMIT() asm volatile("cp.async.commit_group;" ::: "memory")
#define CP_WAIT1()  asm volatile("cp.async.wait_group 1;" ::: "memory")

#define LDSM4(r, addr)                                                          \
    asm volatile("ldmatrix.sync.aligned.m8n8.x4.shared.b16 {%0,%1,%2,%3}, [%4];"\
                 : "=r"((r)[0]), "=r"((r)[1]), "=r"((r)[2]), "=r"((r)[3])       \
                 : "r"(addr))
#define LDSM2(r, addr)                                                          \
    asm volatile("ldmatrix.sync.aligned.m8n8.x2.shared.b16 {%0,%1}, [%2];"      \
                 : "=r"((r)[0]), "=r"((r)[1]) : "r"(addr))

#define MMA_BF16(d, a, b)                                                       \
    asm volatile("mma.sync.aligned.m16n8k16.row.col.f32.bf16.bf16.f32 "         \
                 "{%0,%1,%2,%3}, {%4,%5,%6,%7}, {%8,%9}, {%0,%1,%2,%3};"        \
                 : "+f"((d)[0]), "+f"((d)[1]), "+f"((d)[2]), "+f"((d)[3])       \
                 : "r"((a)[0]), "r"((a)[1]), "r"((a)[2]), "r"((a)[3]),          \
                   "r"((b)[0]), "r"((b)[1]))

// ---------------------------------------------------------------------------
// Fused: per-row inverse L2 norm + fp32 -> bf16 hi/lo split. One warp per row.
// src [rows][256] f32 -> dst [rows][512] bf16 (cols 0..255 hi, 256..511 lo)
// ---------------------------------------------------------------------------
__device__ __forceinline__ void split_write4(__nv_bfloat16* drow, int col, float4 v) {
    float xs[4] = {v.x, v.y, v.z, v.w};
    uint32_t hp[2], lp[2];
#pragma unroll
    for (int q = 0; q < 2; ++q) {
        __nv_bfloat16 h0 = __float2bfloat16_rn(xs[2 * q + 0]);
        __nv_bfloat16 h1 = __float2bfloat16_rn(xs[2 * q + 1]);
        __nv_bfloat16 l0 = __float2bfloat16_rn(xs[2 * q + 0] - __bfloat162float(h0));
        __nv_bfloat16 l1 = __float2bfloat16_rn(xs[2 * q + 1] - __bfloat162float(h1));
        hp[q] = (uint32_t)__bfloat16_as_ushort(h0) | ((uint32_t)__bfloat16_as_ushort(h1) << 16);
        lp[q] = (uint32_t)__bfloat16_as_ushort(l0) | ((uint32_t)__bfloat16_as_ushort(l1) << 16);
    }
    *(uint2*)(drow + col)       = make_uint2(hp[0], hp[1]);
    *(uint2*)(drow + 256 + col) = make_uint2(lp[0], lp[1]);
}

__global__ void norm_split_kernel(const float* __restrict__ x,
                                  __nv_bfloat16* __restrict__ dst,
                                  float* __restrict__ inv, int rows) {
    int warp = (blockIdx.x * blockDim.x + threadIdx.x) >> 5;
    int lane = threadIdx.x & 31;
    if (warp >= rows) return;
    const float4* p = (const float4*)(x + (size_t)warp * DD);
    float4 v0 = p[lane];
    float4 v1 = p[lane + 32];
    float s = v0.x * v0.x + v0.y * v0.y + v0.z * v0.z + v0.w * v0.w
            + v1.x * v1.x + v1.y * v1.y + v1.z * v1.z + v1.w * v1.w;
#pragma unroll
    for (int o = 16; o; o >>= 1) s += __shfl_xor_sync(0xFFFFFFFFu, s, o);
    if (lane == 0) inv[warp] = 1.0f / fmaxf(sqrtf(s), 1e-12f);

    __nv_bfloat16* drow = dst + (size_t)warp * 512;
    split_write4(drow, lane * 4, v0);
    split_write4(drow, lane * 4 + 128, v1);
}

// ---------------------------------------------------------------------------
// HMMA GEMM (legacy tensor path, sm_80-compatible PTX):
// C[k,m,n] = split-dot * invF * invM.  CTA tile 128x128, K chunks of 32 bf16,
// 3 terms x 8 chunks = 24 chunks. 3-stage cp.async ring. 8 warps = 2x4.
// ---------------------------------------------------------------------------
#define BM 128
#define BN 128
#define NCHUNK 24
#define STAGES 3
#define ROWPAD 40                         // bf16 elems per smem row (80 B)
#define TILE_BYTES (128 * ROWPAD * 2)     // 10240
#define STAGE_BYTES (2 * TILE_BYTES)      // A tile + B tile
#define GEMM_SMEM (STAGES * STAGE_BYTES + 1024)

__global__ void __launch_bounds__(256)
gemm_hmma_kernel(const __nv_bfloat16* __restrict__ Asp,
                 const __nv_bfloat16* __restrict__ Bsp,
                 float* __restrict__ C,
                 const float* __restrict__ invF,
                 const float* __restrict__ invM) {
    extern __shared__ char smem[];
    const int k  = blockIdx.z;
    const int m0 = blockIdx.y * BM;
    const int n0 = blockIdx.x * BN;
    const int tid = threadIdx.x;
    const int wid = tid >> 5, lid = tid & 31;

    float* invFsm = (float*)(smem + STAGES * STAGE_BYTES);
    float* invMsm = invFsm + 128;
    if (tid < 128) {
        invFsm[tid] = invF[k * BB + m0 + tid];
    } else {
        int t = tid - 128;
        int n = n0 + t;
        invMsm[t] = (n < NN) ? invM[k * NN + n] : 0.0f;
    }

    const __nv_bfloat16* Ak = Asp + (size_t)k * BB * 512;
    const __nv_bfloat16* Bk = Bsp + (size_t)k * NN * 512;
    const uint32_t sbase = smem_u32(smem);

    // issue cp.async for one K-chunk (A: 128x32, B: 128x32 bf16)
    auto issue_chunk = [&](int c) {
        const int t  = c >> 3;            // term
        const int kc = c & 7;
        const int aoff = ((t == 1) ? 256 : 0) + kc * 32;
        const int boff = ((t == 2) ? 256 : 0) + kc * 32;
        const uint32_t s = sbase + (c % STAGES) * STAGE_BYTES;
#pragma unroll
        for (int it = 0; it < 2; ++it) {
            int i = tid + it * 256;
            int row = i >> 2, seg = i & 3;
            uint32_t dstA = s + row * 80 + seg * 16;
            const void* srcA = Ak + (size_t)(m0 + row) * 512 + aoff + seg * 8;
            CP16(dstA, srcA);
            int gr = min(n0 + row, NN - 1);
            uint32_t dstB = s + TILE_BYTES + row * 80 + seg * 16;
            const void* srcB = Bk + (size_t)gr * 512 + boff + seg * 8;
            CP16(dstB, srcB);
        }
        CP_COMMIT();
    };

    float acc[4][4][4];
#pragma unroll
    for (int mt = 0; mt < 4; ++mt)
#pragma unroll
        for (int nt = 0; nt < 4; ++nt)
#pragma unroll
            for (int r = 0; r < 4; ++r) acc[mt][nt][r] = 0.0f;

    issue_chunk(0);
    issue_chunk(1);

    const int warp_m = wid >> 2;     // 0..1 (64 rows each)
    const int warp_n = wid & 3;      // 0..3 (32 cols each)

    for (int c = 0; c < NCHUNK; ++c) {
        CP_WAIT1();
        __syncthreads();
        if (c + 2 < NCHUNK) issue_chunk(c + 2);

        const uint32_t sA = sbase + (c % STAGES) * STAGE_BYTES;
        const uint32_t sB = sA + TILE_BYTES;
#pragma unroll
        for (int ks = 0; ks < 2; ++ks) {
            uint32_t a[4][4], b[4][2];
#pragma unroll
            for (int mt = 0; mt < 4; ++mt) {
                int row = warp_m * 64 + mt * 16 + (lid & 15);
                int col = ks * 16 + (lid >> 4) * 8;
                LDSM4(a[mt], sA + row * 80 + col * 2);
            }
#pragma unroll
            for (int nt = 0; nt < 4; ++nt) {
                int row = warp_n * 32 + nt * 8 + (lid & 7);
                int col = ks * 16 + ((lid >> 3) & 1) * 8;
                LDSM2(b[nt], sB + row * 80 + col * 2);
            }
#pragma unroll
            for (int mt = 0; mt < 4; ++mt)
#pragma unroll
                for (int nt = 0; nt < 4; ++nt)
                    MMA_BF16(acc[mt][nt], a[mt], b[nt]);
        }
    }
    __syncthreads();

    // epilogue: d frag mapping c0:(g,tig*2) c1:(g,tig*2+1) c2:(g+8,..) c3
    const int g = lid >> 2, tig = lid & 3;
#pragma unroll
    for (int mt = 0; mt < 4; ++mt) {
        int mA = warp_m * 64 + mt * 16;
        float fi0 = invFsm[mA + g];
        float fi1 = invFsm[mA + g + 8];
        float* r0 = C + ((size_t)k * BB + m0 + mA + g) * NN;
        float* r1 = C + ((size_t)k * BB + m0 + mA + g + 8) * NN;
#pragma unroll
        for (int nt = 0; nt < 4; ++nt) {
            int nA = warp_n * 32 + nt * 8 + tig * 2;
            int n = n0 + nA;
            if (n + 1 < NN) {
                float im0 = invMsm[nA], im1 = invMsm[nA + 1];
                *(float2*)(r0 + n) = make_float2(acc[mt][nt][0] * fi0 * im0,
                                                 acc[mt][nt][1] * fi0 * im1);
                *(float2*)(r1 + n) = make_float2(acc[mt][nt][2] * fi1 * im0,
                                                 acc[mt][nt][3] * fi1 * im1);
            } else if (n < NN) {
                float im0 = invMsm[nA];
                r0[n] = acc[mt][nt][0] * fi0 * im0;
                r1[n] = acc[mt][nt][2] * fi1 * im0;
            }
        }
    }
}

// ---------------------------------------------------------------------------
// Per (k,b) row: top-5 of 50000, softmax over the 5, scatter into soft_labels
// ---------------------------------------------------------------------------
__global__ void __launch_bounds__(256)
topk_kernel(const float* __restrict__ sim, float* __restrict__ soft) {
    const int row = blockIdx.x;
    const float* s = sim + (size_t)row * NN;
    const int tid = threadIdx.x;

    float tv[TOPK];
    int   ti[TOPK];
#pragma unroll
    for (int i = 0; i < TOPK; ++i) { tv[i] = -3.0e38f; ti[i] = -1; }

    auto insert = [&](float v, int idx) {
        if (v > tv[TOPK - 1]) {
            tv[TOPK - 1] = v; ti[TOPK - 1] = idx;
#pragma unroll
            for (int p = TOPK - 1; p > 0; --p) {
                if (tv[p] > tv[p - 1]) {
                    float t = tv[p]; tv[p] = tv[p - 1]; tv[p - 1] = t;
                    int   q = ti[p]; ti[p] = ti[p - 1]; ti[p - 1] = q;
                }
            }
        }
    };

    const float4* s4 = (const float4*)s;
    for (int i = tid; i < NN / 4; i += 256) {
        float4 v = s4[i];
        // fast reject: most vectors contain nothing above current 5th-best
        float m4 = fmaxf(fmaxf(v.x, v.y), fmaxf(v.z, v.w));
        if (m4 > tv[TOPK - 1]) {
            int b = 4 * i;
            insert(v.x, b + 0);
            insert(v.y, b + 1);
            insert(v.z, b + 2);
            insert(v.w, b + 3);
        }
    }

    __shared__ float sv[256 * TOPK];
    __shared__ int   si[256 * TOPK];
    __shared__ float rv[256];
    __shared__ int   ri[256];
    __shared__ float winV[TOPK];
    __shared__ int   winI[TOPK];

#pragma unroll
    for (int i = 0; i < TOPK; ++i) {
        sv[tid * TOPK + i] = tv[i];
        si[tid * TOPK + i] = ti[i];
    }
    __syncthreads();

    for (int r = 0; r < TOPK; ++r) {
        float m = -3.0e38f; int ms = -1;
#pragma unroll
        for (int j = 0; j < TOPK; ++j) {
            int slot = tid * TOPK + j;
            if (sv[slot] > m) { m = sv[slot]; ms = slot; }
        }
        rv[tid] = m; ri[tid] = ms;
        __syncthreads();
        for (int off = 128; off; off >>= 1) {
            if (tid < off && rv[tid + off] > rv[tid]) {
                rv[tid] = rv[tid + off]; ri[tid] = ri[tid + off];
            }
            __syncthreads();
        }
        if (tid == 0) {
            int slot = ri[0];
            winV[r] = rv[0];
            winI[r] = si[slot];
            sv[slot] = -3.0e38f;
        }
        __syncthreads();
    }

    if (tid == 0) {
        float mx = winV[0];
        float w[TOPK], sum = 0.0f;
#pragma unroll
        for (int i = 0; i < TOPK; ++i) {
            w[i] = __expf((winV[i] - mx) * (1.0f / 3.0f));
            sum += w[i];
        }
        float invSum = 1.0f / sum;
        float* srow = soft + (size_t)row * NN;
#pragma unroll
        for (int i = 0; i < TOPK; ++i)
            srow[winI[i]] = w[i] * invSum;
    }
}

// ---------------------------------------------------------------------------
extern "C" void kernel_launch(void* const* d_in, const int* in_sizes, int n_in,
                              void* d_out, int out_size) {
    const float* feat = (const float*)d_in[0];  // [KP,BB,DD]
    const float* mem  = (const float*)d_in[1];  // [KP,NN,DD]
    float* out = (float*)d_out;

    const size_t total = (size_t)KP * BB * NN;

    float *invF, *invM;
    __nv_bfloat16 *Asp, *Bsp;
    cudaGetSymbolAddress((void**)&invF, g_invF);
    cudaGetSymbolAddress((void**)&invM, g_invM);
    cudaGetSymbolAddress((void**)&Asp, g_Asplit);
    cudaGetSymbolAddress((void**)&Bsp, g_Bsplit);

    float* soft = out;
    float* sim;
    if ((size_t)out_size >= 2 * total) {
        sim = out + total;
    } else {
        cudaGetSymbolAddress((void**)&sim, g_simScratch);
    }

    cudaMemsetAsync(soft, 0, total * sizeof(float), 0);

    // fused norm + bf16 hi/lo split
    {
        int rowsF = KP * BB;
        norm_split_kernel<<<(rowsF + 7) / 8, 256>>>(feat, Asp, invF, rowsF);
        int rowsM = KP * NN;
        norm_split_kernel<<<(rowsM + 7) / 8, 256>>>(mem, Bsp, invM, rowsM);
    }

    // HMMA GEMM
    {
        cudaFuncSetAttribute(gemm_hmma_kernel,
                             cudaFuncAttributeMaxDynamicSharedMemorySize, GEMM_SMEM);
        dim3 grid((NN + BN - 1) / BN, BB / BM, KP);  // (391, 2, 6)
        gemm_hmma_kernel<<<grid, 256, GEMM_SMEM>>>(Asp, Bsp, sim, invF, invM);
    }

    // top-5 + softmax scatter
    topk_kernel<<<KP * BB, 256>>>(sim, soft);
}

// round 5
// speedup vs baseline: 2.7556x; 1.0235x over previous
#include <cuda_runtime.h>
#include <cuda_bf16.h>
#include <cstdint>

#define KP 6
#define BB 256
#define DD 256
#define NN 50000
#define TOPK 5

// ---------------------------------------------------------------------------
// static device scratch
// ---------------------------------------------------------------------------
__device__ float g_invF[KP * BB];
__device__ float g_invM[KP * NN];
__device__ __nv_bfloat16 g_Asplit[(size_t)KP * BB * 512];   // [k][m][hi(256)|lo(256)]
__device__ __nv_bfloat16 g_Bsplit[(size_t)KP * NN * 512];   // [k][n][hi(256)|lo(256)]
__device__ float g_simScratch[(size_t)KP * BB * NN];        // fallback only

// ---------------------------------------------------------------------------
// helpers
// ---------------------------------------------------------------------------
__device__ __forceinline__ uint32_t smem_u32(const void* p) {
    uint32_t a;
    asm("{ .reg .u64 t; cvta.to.shared.u64 t, %1; cvt.u32.u64 %0, t; }"
        : "=r"(a) : "l"(p));
    return a;
}

#define CP16(dst, src) \
    asm volatile("cp.async.cg.shared.global [%0], [%1], 16;" \
                 :: "r"(dst), "l"(src) : "memory")
#define CP_COMMIT() asm volatile("cp.async.commit_group;" ::: "memory")
#define CP_WAIT3()  asm volatile("cp.async.wait_group 3;" ::: "memory")

#define LDSM4(r, addr)                                                          \
    asm volatile("ldmatrix.sync.aligned.m8n8.x4.shared.b16 {%0,%1,%2,%3}, [%4];"\
                 : "=r"((r)[0]), "=r"((r)[1]), "=r"((r)[2]), "=r"((r)[3])       \
                 : "r"(addr))

#define MMA_BF16(d, a, b)                                                       \
    asm volatile("mma.sync.aligned.m16n8k16.row.col.f32.bf16.bf16.f32 "         \
                 "{%0,%1,%2,%3}, {%4,%5,%6,%7}, {%8,%9}, {%0,%1,%2,%3};"        \
                 : "+f"((d)[0]), "+f"((d)[1]), "+f"((d)[2]), "+f"((d)[3])       \
                 : "r"((a)[0]), "r"((a)[1]), "r"((a)[2]), "r"((a)[3]),          \
                   "r"((b)[0]), "r"((b)[1]))

// ---------------------------------------------------------------------------
// Fused: per-row inverse L2 norm + fp32 -> bf16 hi/lo split. One warp per row.
// ---------------------------------------------------------------------------
__device__ __forceinline__ void split_write4(__nv_bfloat16* drow, int col, float4 v) {
    float xs[4] = {v.x, v.y, v.z, v.w};
    uint32_t hp[2], lp[2];
#pragma unroll
    for (int q = 0; q < 2; ++q) {
        __nv_bfloat16 h0 = __float2bfloat16_rn(xs[2 * q + 0]);
        __nv_bfloat16 h1 = __float2bfloat16_rn(xs[2 * q + 1]);
        __nv_bfloat16 l0 = __float2bfloat16_rn(xs[2 * q + 0] - __bfloat162float(h0));
        __nv_bfloat16 l1 = __float2bfloat16_rn(xs[2 * q + 1] - __bfloat162float(h1));
        hp[q] = (uint32_t)__bfloat16_as_ushort(h0) | ((uint32_t)__bfloat16_as_ushort(h1) << 16);
        lp[q] = (uint32_t)__bfloat16_as_ushort(l0) | ((uint32_t)__bfloat16_as_ushort(l1) << 16);
    }
    *(uint2*)(drow + col)       = make_uint2(hp[0], hp[1]);
    *(uint2*)(drow + 256 + col) = make_uint2(lp[0], lp[1]);
}

__global__ void norm_split_kernel(const float* __restrict__ x,
                                  __nv_bfloat16* __restrict__ dst,
                                  float* __restrict__ inv, int rows) {
    int warp = (blockIdx.x * blockDim.x + threadIdx.x) >> 5;
    int lane = threadIdx.x & 31;
    if (warp >= rows) return;
    const float4* p = (const float4*)(x + (size_t)warp * DD);
    float4 v0 = p[lane];
    float4 v1 = p[lane + 32];
    float s = v0.x * v0.x + v0.y * v0.y + v0.z * v0.z + v0.w * v0.w
            + v1.x * v1.x + v1.y * v1.y + v1.z * v1.z + v1.w * v1.w;
#pragma unroll
    for (int o = 16; o; o >>= 1) s += __shfl_xor_sync(0xFFFFFFFFu, s, o);
    if (lane == 0) inv[warp] = 1.0f / fmaxf(sqrtf(s), 1e-12f);

    __nv_bfloat16* drow = dst + (size_t)warp * 512;
    split_write4(drow, lane * 4, v0);
    split_write4(drow, lane * 4 + 128, v1);
}

// ---------------------------------------------------------------------------
// HMMA GEMM: 128x128 tile, K chunks of 32 bf16, kc-major term order,
// 5-stage cp.async ring w/ depth-4 prefetch. 8 warps = 2x4 (64x32 warp tile).
// ---------------------------------------------------------------------------
#define BM 128
#define BN 128
#define NCHUNK 24
#define STAGES 5
#define TILE_BYTES (128 * 40 * 2)         // 10240 (80B rows, ldsm conflict-free)
#define STAGE_BYTES (2 * TILE_BYTES)
#define GEMM_SMEM (STAGES * STAGE_BYTES + 1024)

__global__ void __launch_bounds__(256)
gemm_hmma_kernel(const __nv_bfloat16* __restrict__ Asp,
                 const __nv_bfloat16* __restrict__ Bsp,
                 float* __restrict__ C,
                 const float* __restrict__ invF,
                 const float* __restrict__ invM) {
    extern __shared__ char smem[];
    const int k  = blockIdx.z;
    const int m0 = blockIdx.y * BM;
    const int n0 = blockIdx.x * BN;
    const int tid = threadIdx.x;
    const int wid = tid >> 5, lid = tid & 31;

    float* invFsm = (float*)(smem + STAGES * STAGE_BYTES);
    float* invMsm = invFsm + 128;
    if (tid < 128) {
        invFsm[tid] = invF[k * BB + m0 + tid];
    } else {
        int t = tid - 128;
        int n = n0 + t;
        invMsm[t] = (n < NN) ? invM[k * NN + n] : 0.0f;
    }

    const __nv_bfloat16* Ak = Asp + (size_t)k * BB * 512;
    const __nv_bfloat16* Bk = Bsp + (size_t)k * NN * 512;
    const uint32_t sbase = smem_u32(smem);

    // kc-major chunk order: c -> (kc = c/3, t = c%3). t0/t1 share the B-hi
    // chunk back-to-back (L2 reuse); t0/t2 share the A-hi chunk (A tiny).
    auto issue_chunk = [&](int c) {
        const int t  = c % 3;
        const int kc = c / 3;
        const int aoff = ((t == 1) ? 256 : 0) + kc * 32;
        const int boff = ((t == 2) ? 256 : 0) + kc * 32;
        const uint32_t s = sbase + (c % STAGES) * STAGE_BYTES;
#pragma unroll
        for (int it = 0; it < 2; ++it) {
            int i = tid + it * 256;
            int row = i >> 2, seg = i & 3;
            uint32_t dstA = s + row * 80 + seg * 16;
            const void* srcA = Ak + (size_t)(m0 + row) * 512 + aoff + seg * 8;
            CP16(dstA, srcA);
            int gr = min(n0 + row, NN - 1);
            uint32_t dstB = s + TILE_BYTES + row * 80 + seg * 16;
            const void* srcB = Bk + (size_t)gr * 512 + boff + seg * 8;
            CP16(dstB, srcB);
        }
        CP_COMMIT();
    };

    float acc[4][4][4];
#pragma unroll
    for (int mt = 0; mt < 4; ++mt)
#pragma unroll
        for (int nt = 0; nt < 4; ++nt)
#pragma unroll
            for (int r = 0; r < 4; ++r) acc[mt][nt][r] = 0.0f;

#pragma unroll
    for (int c = 0; c < 4; ++c) issue_chunk(c);

    const int warp_m = wid >> 2;     // 0..1 (64 rows)
    const int warp_n = wid & 3;      // 0..3 (32 cols)

    for (int c = 0; c < NCHUNK; ++c) {
        CP_WAIT3();
        __syncthreads();
        if (c + 4 < NCHUNK) issue_chunk(c + 4);

        const uint32_t sA = sbase + (c % STAGES) * STAGE_BYTES;
        const uint32_t sB = sA + TILE_BYTES;
#pragma unroll
        for (int ks = 0; ks < 2; ++ks) {
            uint32_t a[4][4], b[4][2];
#pragma unroll
            for (int mt = 0; mt < 4; ++mt) {
                int row = warp_m * 64 + mt * 16 + (lid & 15);
                int col = ks * 16 + (lid >> 4) * 8;
                LDSM4(a[mt], sA + row * 80 + col * 2);
            }
#pragma unroll
            for (int np = 0; np < 2; ++np) {
                // x4 ldsm covering nt = np*2 and np*2+1 (both k-halves)
                uint32_t bb[4];
                int grp = lid >> 3, r = lid & 7;
                int row = warp_n * 32 + np * 16 + (grp >> 1) * 8 + r;
                int col = ks * 16 + (grp & 1) * 8;
                LDSM4(bb, sB + row * 80 + col * 2);
                b[np * 2 + 0][0] = bb[0]; b[np * 2 + 0][1] = bb[1];
                b[np * 2 + 1][0] = bb[2]; b[np * 2 + 1][1] = bb[3];
            }
#pragma unroll
            for (int mt = 0; mt < 4; ++mt)
#pragma unroll
                for (int nt = 0; nt < 4; ++nt)
                    MMA_BF16(acc[mt][nt], a[mt], b[nt]);
        }
    }
    __syncthreads();

    // epilogue
    const int g = lid >> 2, tig = lid & 3;
#pragma unroll
    for (int mt = 0; mt < 4; ++mt) {
        int mA = warp_m * 64 + mt * 16;
        float fi0 = invFsm[mA + g];
        float fi1 = invFsm[mA + g + 8];
        float* r0 = C + ((size_t)k * BB + m0 + mA + g) * NN;
        float* r1 = C + ((size_t)k * BB + m0 + mA + g + 8) * NN;
#pragma unroll
        for (int nt = 0; nt < 4; ++nt) {
            int nA = warp_n * 32 + nt * 8 + tig * 2;
            int n = n0 + nA;
            if (n + 1 < NN) {
                float im0 = invMsm[nA], im1 = invMsm[nA + 1];
                *(float2*)(r0 + n) = make_float2(acc[mt][nt][0] * fi0 * im0,
                                                 acc[mt][nt][1] * fi0 * im1);
                *(float2*)(r1 + n) = make_float2(acc[mt][nt][2] * fi1 * im0,
                                                 acc[mt][nt][3] * fi1 * im1);
            } else if (n < NN) {
                float im0 = invMsm[nA];
                r0[n] = acc[mt][nt][0] * fi0 * im0;
                r1[n] = acc[mt][nt][2] * fi1 * im0;
            }
        }
    }
}

// ---------------------------------------------------------------------------
// Per (k,b) row: top-5 of 50000, softmax, scatter. ILP-2 float4 stream.
// ---------------------------------------------------------------------------
__global__ void __launch_bounds__(256)
topk_kernel(const float* __restrict__ sim, float* __restrict__ soft) {
    const int row = blockIdx.x;
    const float* s = sim + (size_t)row * NN;
    const int tid = threadIdx.x;

    float tv[TOPK];
    int   ti[TOPK];
#pragma unroll
    for (int i = 0; i < TOPK; ++i) { tv[i] = -3.0e38f; ti[i] = -1; }

    auto insert = [&](float v, int idx) {
        if (v > tv[TOPK - 1]) {
            tv[TOPK - 1] = v; ti[TOPK - 1] = idx;
#pragma unroll
            for (int p = TOPK - 1; p > 0; --p) {
                if (tv[p] > tv[p - 1]) {
                    float t = tv[p]; tv[p] = tv[p - 1]; tv[p - 1] = t;
                    int   q = ti[p]; ti[p] = ti[p - 1]; ti[p - 1] = q;
                }
            }
        }
    };
    auto scan4 = [&](float4 v, int b) {
        float m4 = fmaxf(fmaxf(v.x, v.y), fmaxf(v.z, v.w));
        if (m4 > tv[TOPK - 1]) {
            insert(v.x, b + 0);
            insert(v.y, b + 1);
            insert(v.z, b + 2);
            insert(v.w, b + 3);
        }
    };

    const float4* s4 = (const float4*)s;
    const int NV = NN / 4;  // 12500
    int i = tid;
    for (; i + 256 < NV; i += 512) {
        float4 v0 = s4[i];
        float4 v1 = s4[i + 256];
        scan4(v0, 4 * i);
        scan4(v1, 4 * (i + 256));
    }
    if (i < NV) scan4(s4[i], 4 * i);

    __shared__ float sv[256 * TOPK];
    __shared__ int   si[256 * TOPK];
    __shared__ float rv[256];
    __shared__ int   ri[256];
    __shared__ float winV[TOPK];
    __shared__ int   winI[TOPK];

#pragma unroll
    for (int q = 0; q < TOPK; ++q) {
        sv[tid * TOPK + q] = tv[q];
        si[tid * TOPK + q] = ti[q];
    }
    __syncthreads();

    for (int r = 0; r < TOPK; ++r) {
        float m = -3.0e38f; int ms = -1;
#pragma unroll
        for (int j = 0; j < TOPK; ++j) {
            int slot = tid * TOPK + j;
            if (sv[slot] > m) { m = sv[slot]; ms = slot; }
        }
        rv[tid] = m; ri[tid] = ms;
        __syncthreads();
        for (int off = 128; off; off >>= 1) {
            if (tid < off && rv[tid + off] > rv[tid]) {
                rv[tid] = rv[tid + off]; ri[tid] = ri[tid + off];
            }
            __syncthreads();
        }
        if (tid == 0) {
            int slot = ri[0];
            winV[r] = rv[0];
            winI[r] = si[slot];
            sv[slot] = -3.0e38f;
        }
        __syncthreads();
    }

    if (tid == 0) {
        float mx = winV[0];
        float w[TOPK], sum = 0.0f;
#pragma unroll
        for (int q = 0; q < TOPK; ++q) {
            w[q] = __expf((winV[q] - mx) * (1.0f / 3.0f));
            sum += w[q];
        }
        float invSum = 1.0f / sum;
        float* srow = soft + (size_t)row * NN;
#pragma unroll
        for (int q = 0; q < TOPK; ++q)
            srow[winI[q]] = w[q] * invSum;
    }
}

// ---------------------------------------------------------------------------
extern "C" void kernel_launch(void* const* d_in, const int* in_sizes, int n_in,
                              void* d_out, int out_size) {
    const float* feat = (const float*)d_in[0];  // [KP,BB,DD]
    const float* mem  = (const float*)d_in[1];  // [KP,NN,DD]
    float* out = (float*)d_out;

    const size_t total = (size_t)KP * BB * NN;

    float *invF, *invM;
    __nv_bfloat16 *Asp, *Bsp;
    cudaGetSymbolAddress((void**)&invF, g_invF);
    cudaGetSymbolAddress((void**)&invM, g_invM);
    cudaGetSymbolAddress((void**)&Asp, g_Asplit);
    cudaGetSymbolAddress((void**)&Bsp, g_Bsplit);

    float* soft = out;
    float* sim;
    if ((size_t)out_size >= 2 * total) {
        sim = out + total;
    } else {
        cudaGetSymbolAddress((void**)&sim, g_simScratch);
    }

    cudaMemsetAsync(soft, 0, total * sizeof(float), 0);

    // fused norm + bf16 hi/lo split
    {
        int rowsF = KP * BB;
        norm_split_kernel<<<(rowsF + 7) / 8, 256>>>(feat, Asp, invF, rowsF);
        int rowsM = KP * NN;
        norm_split_kernel<<<(rowsM + 7) / 8, 256>>>(mem, Bsp, invM, rowsM);
    }

    // HMMA GEMM
    {
        cudaFuncSetAttribute(gemm_hmma_kernel,
                             cudaFuncAttributeMaxDynamicSharedMemorySize, GEMM_SMEM);
        dim3 grid((NN + BN - 1) / BN, BB / BM, KP);  // (391, 2, 6)
        gemm_hmma_kernel<<<grid, 256, GEMM_SMEM>>>(Asp, Bsp, sim, invF, invM);
    }

    // top-5 + softmax scatter
    topk_kernel<<<KP * BB, 256>>>(sim, soft);
}